// round 1
// baseline (speedup 1.0000x reference)
#include <cuda_runtime.h>
#include <cuda_bf16.h>

// ---------------------------------------------------------------------------
// MiddleLayerDecoder — round 0
//
// Pipeline (N=50000 nodes, K=8 pts, M=400000 point rows):
//   h1    = relu(X @ Wg0 + bg0)            [N,256]
//   h2    = relu(h1 @ Wg1 + bg1)           [N,128]
//   feats = relu(h2 @ Wg2 + bg2)           [N,64]
//   rel   = feats @ Wdec + bdec            [N,24] == [N*K,3]  -> d_out[0:1.2M]
//   T     = X @ W0a + b0                   [N,256]   (W0a = W0 rows 0..255)
//   A     = T + feats @ W0b                [N,256]   (W0b = W0 rows 256..319)
//   h0    = relu(A[node] + rel @ W0c)      [M,256]   (W0c = W0 rows 320..322)
//   p1    = relu(h0 @ W1 + b1)             [M,256]
//   dec   = relu(p1 @ W2 + b2)             [M,256]  -> d_out[1.2M : 103.6M]
//   cluster = float(i>>3)                  [M]      -> d_out[103.6M : 104M]
// ---------------------------------------------------------------------------

#define N_NODES 50000
#define KPTS 8
#define M_PTS (N_NODES * KPTS)

// scratch (static device allocations; no cudaMalloc anywhere)
__device__ float g_h1[N_NODES * 256];
__device__ float g_h2[N_NODES * 128];
__device__ float g_feats[N_NODES * 64];
__device__ float g_T[N_NODES * 256];
__device__ float g_A[N_NODES * 256];
__device__ float g_h0[(size_t)M_PTS * 256];
__device__ float g_p1[(size_t)M_PTS * 256];

// ---------------------------------------------------------------------------
// Generic tiled SGEMM: C = act(A[M,K] @ B[K,N] + bias + Cin)
// BM=BN=128, BK=8, 256 threads, 8x8 register tile per thread.
// ---------------------------------------------------------------------------
__global__ __launch_bounds__(256)
void sgemm128(const float* __restrict__ A, const float* __restrict__ B,
              const float* __restrict__ bias, const float* __restrict__ Cin,
              float* __restrict__ C, int M, int N, int K, int doRelu)
{
    const int BM = 128, BN = 128, BK = 8, TM = 8, TN = 8;
    __shared__ float As[BK][BM];
    __shared__ float Bs[BK][BN];

    const int block_row = blockIdx.y;
    const int block_col = blockIdx.x;
    const int tid = threadIdx.x;
    const int tr = tid / 16;        // 0..15
    const int tc = tid % 16;        // 0..15

    float acc[TM][TN];
#pragma unroll
    for (int i = 0; i < TM; i++)
#pragma unroll
        for (int j = 0; j < TN; j++) acc[i][j] = 0.f;

    // A tile load mapping: 128 rows x 8 cols, 2 threads/row, 4 elems each
    const int aRow  = tid >> 1;
    const int aCol4 = (tid & 1) * 4;
    // B tile load mapping: 8 rows x 128 cols, 32 threads/row, 4 elems each
    const int bRow  = tid >> 5;
    const int bCol4 = (tid & 31) * 4;

    const long gArowBase = (long)block_row * BM + aRow;
    const long gBcolBase = (long)block_col * BN + bCol4;

    for (int k0 = 0; k0 < K; k0 += BK) {
#pragma unroll
        for (int i = 0; i < 4; i++) {
            int gk = k0 + aCol4 + i;
            float v = 0.f;
            if (gArowBase < M && gk < K) v = A[gArowBase * K + gk];
            As[aCol4 + i][aRow] = v;
        }
        {
            int gk = k0 + bRow;
#pragma unroll
            for (int i = 0; i < 4; i++) {
                long gc = gBcolBase + i;
                float v = 0.f;
                if (gk < K && gc < N) v = B[(long)gk * N + gc];
                Bs[bRow][bCol4 + i] = v;
            }
        }
        __syncthreads();

#pragma unroll
        for (int k = 0; k < BK; k++) {
            float a[TM], b[TN];
#pragma unroll
            for (int i = 0; i < TM; i++) a[i] = As[k][tr * TM + i];
#pragma unroll
            for (int j = 0; j < TN; j++) b[j] = Bs[k][tc * TN + j];
#pragma unroll
            for (int i = 0; i < TM; i++)
#pragma unroll
                for (int j = 0; j < TN; j++)
                    acc[i][j] = fmaf(a[i], b[j], acc[i][j]);
        }
        __syncthreads();
    }

    // epilogue
#pragma unroll
    for (int i = 0; i < TM; i++) {
        long r = (long)block_row * BM + tr * TM + i;
        if (r >= M) continue;
#pragma unroll
        for (int j = 0; j < TN; j++) {
            long c = (long)block_col * BN + tc * TN + j;
            if (c >= N) continue;
            float v = acc[i][j];
            if (bias) v += bias[c];
            if (Cin)  v += Cin[r * N + c];
            if (doRelu) v = fmaxf(v, 0.f);
            C[r * N + c] = v;
        }
    }
}

// ---------------------------------------------------------------------------
// h0[p, j] = relu(A[p/8, j] + sum_t rel[p,t] * W0c[t,j]),  vectorized float4
// ---------------------------------------------------------------------------
__global__ __launch_bounds__(256)
void point_layer0(const float* __restrict__ A, const float* __restrict__ rel,
                  const float* __restrict__ W0c, float* __restrict__ h0)
{
    long idx = (long)blockIdx.x * blockDim.x + threadIdx.x;   // one per 4 outputs
    long total = (long)M_PTS * 64;
    if (idx >= total) return;
    long p  = idx >> 6;
    int  j4 = (int)(idx & 63) << 2;
    long node = p >> 3;

    float r0 = rel[p * 3 + 0];
    float r1 = rel[p * 3 + 1];
    float r2 = rel[p * 3 + 2];

    float4 a  = *(const float4*)(A + node * 256 + j4);
    float4 w0 = *(const float4*)(W0c + 0   + j4);
    float4 w1 = *(const float4*)(W0c + 256 + j4);
    float4 w2 = *(const float4*)(W0c + 512 + j4);

    float4 o;
    o.x = fmaxf(a.x + r0 * w0.x + r1 * w1.x + r2 * w2.x, 0.f);
    o.y = fmaxf(a.y + r0 * w0.y + r1 * w1.y + r2 * w2.y, 0.f);
    o.z = fmaxf(a.z + r0 * w0.z + r1 * w1.z + r2 * w2.z, 0.f);
    o.w = fmaxf(a.w + r0 * w0.w + r1 * w1.w + r2 * w2.w, 0.f);
    *(float4*)(h0 + p * 256 + j4) = o;
}

__global__ __launch_bounds__(256)
void cluster_kernel(float* __restrict__ out)
{
    int i = blockIdx.x * blockDim.x + threadIdx.x;
    if (i < M_PTS) out[i] = (float)(i >> 3);
}

// ---------------------------------------------------------------------------
// launch
// ---------------------------------------------------------------------------
static inline dim3 gemm_grid(int M, int N) {
    return dim3((N + 127) / 128, (M + 127) / 128);
}

extern "C" void kernel_launch(void* const* d_in, const int* in_sizes, int n_in,
                              void* d_out, int out_size)
{
    const float* X    = (const float*)d_in[0];   // [50000,256]
    const float* Wg0  = (const float*)d_in[1];
    const float* bg0  = (const float*)d_in[2];
    const float* Wg1  = (const float*)d_in[3];
    const float* bg1  = (const float*)d_in[4];
    const float* Wg2  = (const float*)d_in[5];
    const float* bg2  = (const float*)d_in[6];
    const float* Wdec = (const float*)d_in[7];   // [64,24]
    const float* bdec = (const float*)d_in[8];
    const float* W0   = (const float*)d_in[9];   // [323,256]
    const float* b0   = (const float*)d_in[10];
    const float* W1   = (const float*)d_in[11];  // [256,256]
    const float* b1   = (const float*)d_in[12];
    const float* W2   = (const float*)d_in[13];  // [256,256]
    const float* b2   = (const float*)d_in[14];

    float* out = (float*)d_out;
    float* out_rel     = out;                       // 1,200,000
    float* out_decoded = out + 1200000;             // 102,400,000
    float* out_cluster = out + 1200000 + 102400000; // 400,000

    float *h1, *h2, *feats, *T, *Abuf, *h0, *p1;
    cudaGetSymbolAddress((void**)&h1,    g_h1);
    cudaGetSymbolAddress((void**)&h2,    g_h2);
    cudaGetSymbolAddress((void**)&feats, g_feats);
    cudaGetSymbolAddress((void**)&T,     g_T);
    cudaGetSymbolAddress((void**)&Abuf,  g_A);
    cudaGetSymbolAddress((void**)&h0,    g_h0);
    cudaGetSymbolAddress((void**)&p1,    g_p1);

    const float* W0a = W0;              // rows 0..255
    const float* W0b = W0 + 256 * 256;  // rows 256..319
    const float* W0c = W0 + 320 * 256;  // rows 320..322

    // global MLP
    sgemm128<<<gemm_grid(N_NODES, 256), 256>>>(X,  Wg0, bg0, nullptr, h1,    N_NODES, 256, 256, 1);
    sgemm128<<<gemm_grid(N_NODES, 128), 256>>>(h1, Wg1, bg1, nullptr, h2,    N_NODES, 128, 256, 1);
    sgemm128<<<gemm_grid(N_NODES, 64),  256>>>(h2, Wg2, bg2, nullptr, feats, N_NODES, 64,  128, 1);

    // decoder head -> relative_points (directly into d_out)
    sgemm128<<<gemm_grid(N_NODES, 24), 256>>>(feats, Wdec, bdec, nullptr, out_rel, N_NODES, 24, 64, 0);

    // per-node shared part of point-MLP layer 0
    sgemm128<<<gemm_grid(N_NODES, 256), 256>>>(X,     W0a, b0,      nullptr, T,    N_NODES, 256, 256, 0);
    sgemm128<<<gemm_grid(N_NODES, 256), 256>>>(feats, W0b, nullptr, T,       Abuf, N_NODES, 256, 64,  0);

    // per-point fold-in of relative_points
    {
        long total = (long)M_PTS * 64;
        int blocks = (int)((total + 255) / 256);
        point_layer0<<<blocks, 256>>>(Abuf, out_rel, W0c, h0);
    }

    // point-MLP layers 1 & 2
    sgemm128<<<gemm_grid(M_PTS, 256), 256>>>(h0, W1, b1, nullptr, p1,          M_PTS, 256, 256, 1);
    sgemm128<<<gemm_grid(M_PTS, 256), 256>>>(p1, W2, b2, nullptr, out_decoded, M_PTS, 256, 256, 1);

    // cluster ids
    cluster_kernel<<<(M_PTS + 255) / 256, 256>>>(out_cluster);
}

// round 5
// speedup vs baseline: 3.0294x; 3.0294x over previous
#include <cuda_runtime.h>
#include <cuda_bf16.h>
#include <cstdint>

// ---------------------------------------------------------------------------
// MiddleLayerDecoder — round 3: mma.sync (HMMA) bf16 hi/lo split GEMMs.
// R2 bug fixed: B planes now stored [K][N] (n-contiguous) and ldmatrix.trans
// is issued on k-rows, matching the mma.sync .col B fragment.
// ---------------------------------------------------------------------------

#define N_NODES 50000
#define KPTS 8
#define M_PTS (N_NODES * KPTS)

// ---- scratch (static device memory; no allocations anywhere) ----
__device__ float g_h1[(size_t)N_NODES * 256];
__device__ float g_h2[(size_t)N_NODES * 128];
__device__ float g_feats[(size_t)N_NODES * 64];
__device__ float g_T[(size_t)N_NODES * 256];
__device__ float g_A[(size_t)N_NODES * 256];
__device__ float g_h0[(size_t)M_PTS * 256];
__device__ float g_p1[(size_t)M_PTS * 256];
__device__ __align__(16) __nv_bfloat16 g_whi[335872];
__device__ __align__(16) __nv_bfloat16 g_wlo[335872];

// weight planes are [Kp][Np] (k rows, n contiguous)
#define OFF_WG0  0        // 256 x 256
#define OFF_WG1  65536    // 256 x 128
#define OFF_WG2  98304    // 128 x 128
#define OFF_WDEC 114688   //  64 x 128
#define OFF_W0A  122880   // 256 x 256
#define OFF_W0B  188416   //  64 x 256
#define OFF_W1   204800   // 256 x 256
#define OFF_W2   270336   // 256 x 256

__device__ __forceinline__ uint32_t smem_u32(const void* p) {
    uint32_t a;
    asm("{ .reg .u64 t; cvta.to.shared.u64 t, %1; cvt.u32.u64 %0, t; }" : "=r"(a) : "l"(p));
    return a;
}
__device__ __forceinline__ uint32_t pack2(__nv_bfloat16 a, __nv_bfloat16 b) {
    return (uint32_t)__bfloat16_as_ushort(a) | ((uint32_t)__bfloat16_as_ushort(b) << 16);
}
__device__ __forceinline__ void ldm_x4(uint32_t* r, uint32_t addr) {
    asm volatile("ldmatrix.sync.aligned.m8n8.x4.shared.b16 {%0,%1,%2,%3}, [%4];"
                 : "=r"(r[0]), "=r"(r[1]), "=r"(r[2]), "=r"(r[3]) : "r"(addr));
}
__device__ __forceinline__ void ldm_x4t(uint32_t* r, uint32_t addr) {
    asm volatile("ldmatrix.sync.aligned.m8n8.x4.trans.shared.b16 {%0,%1,%2,%3}, [%4];"
                 : "=r"(r[0]), "=r"(r[1]), "=r"(r[2]), "=r"(r[3]) : "r"(addr));
}
__device__ __forceinline__ void mma16816(float* c, const uint32_t* a, const uint32_t* b) {
    asm volatile("mma.sync.aligned.m16n8k16.row.col.f32.bf16.bf16.f32 "
                 "{%0,%1,%2,%3}, {%4,%5,%6,%7}, {%8,%9}, {%0,%1,%2,%3};"
                 : "+f"(c[0]), "+f"(c[1]), "+f"(c[2]), "+f"(c[3])
                 : "r"(a[0]), "r"(a[1]), "r"(a[2]), "r"(a[3]), "r"(b[0]), "r"(b[1]));
}

// ---------------------------------------------------------------------------
// SMEM layout:
//   A planes: 128 rows x 64B data, padded to 80B rows  (conflict-free)
//   B planes: 32 k-rows x 256B data, padded to 272B rows (conflict-free)
// ---------------------------------------------------------------------------
#define ASTRIDE 80
#define BSTRIDE 272
#define SA_HI 0
#define SA_LO 10240
#define SB_HI 20480
#define SB_LO 29184
#define SMEM_TOTAL 37888

__global__ __launch_bounds__(256, 1)
void gemm_mma(const float* __restrict__ A,
              const __nv_bfloat16* __restrict__ Bhi,
              const __nv_bfloat16* __restrict__ Blo,
              const float* __restrict__ bias, const float* __restrict__ Cin,
              float* __restrict__ Out,
              int M, int K, int Np, int realN, int ldc, int doRelu)
{
    __shared__ __align__(128) char smem[SMEM_TOTAL];
    const uint32_t sb = smem_u32(smem);
    const int tid = threadIdx.x, lane = tid & 31, wid = tid >> 5;
    const int warpM = (wid & 1) * 64;         // warp row offset in 128
    const int warpN = (wid >> 1) * 32;        // warp col offset in 128
    const long m0 = (long)blockIdx.y * 128;
    const int  n0 = blockIdx.x * 128;
    const int  nc = K >> 5;                   // K chunks of 32

    // prefetch register buffers
    float4 pa[4];
    uint4  pbh[2], pbl[2];

    auto loadA = [&](int k0) {
#pragma unroll
        for (int t = 0; t < 4; t++) {
            const int i = tid + t * 256, row = i >> 3, c4 = i & 7;
            const long gm = m0 + row;
            pa[t] = (gm < M) ? *(const float4*)(A + gm * (long)K + k0 + c4 * 4)
                             : make_float4(0.f, 0.f, 0.f, 0.f);
        }
    };
    // B chunk: 32 k-rows x 128 n; [Kp][Np] global layout
    auto loadB = [&](int k0) {
#pragma unroll
        for (int t = 0; t < 2; t++) {
            const int i = tid + t * 256, row = i >> 4, q = i & 15;
            const long off = (long)(k0 + row) * Np + n0 + q * 8;
            pbh[t] = *(const uint4*)(Bhi + off);
            pbl[t] = *(const uint4*)(Blo + off);
        }
    };

    float acc[4][4][4];
#pragma unroll
    for (int i = 0; i < 4; i++)
#pragma unroll
        for (int j = 0; j < 4; j++)
#pragma unroll
            for (int r = 0; r < 4; r++) acc[i][j][r] = 0.f;

    // ldmatrix addresses
    //   A (row-major, x4): lanes 0-15 -> rows m0..15 (k0-7), lanes 16-31 -> +16B (k8-15)
    const uint32_t aAddr = sb + (uint32_t)((warpM + (lane & 15)) * ASTRIDE + ((lane >> 4) << 4));
    //   B (k-rows, x4 trans): lanes 0-7 -> k0-7, 8-15 -> k8-15, 16-31 -> n+8 block
    const uint32_t bAddr = sb + SB_HI +
        (uint32_t)(((lane & 7) + ((lane >> 3) & 1) * 8) * BSTRIDE +
                   (warpN + ((lane >> 4) << 3)) * 2);

    loadA(0);
    loadB(0);

    for (int c = 0; c < nc; c++) {
        // ---- STS prefetched chunk (fp32 -> bf16 hi/lo split for A) ----
#pragma unroll
        for (int t = 0; t < 4; t++) {
            const int i = tid + t * 256, row = i >> 3, c4 = i & 7;
            const float4 v = pa[t];
            const __nv_bfloat16 hx = __float2bfloat16(v.x), hy = __float2bfloat16(v.y);
            const __nv_bfloat16 hz = __float2bfloat16(v.z), hw = __float2bfloat16(v.w);
            uint2 hp, lp;
            hp.x = pack2(hx, hy); hp.y = pack2(hz, hw);
            lp.x = pack2(__float2bfloat16(v.x - __bfloat162float(hx)),
                         __float2bfloat16(v.y - __bfloat162float(hy)));
            lp.y = pack2(__float2bfloat16(v.z - __bfloat162float(hz)),
                         __float2bfloat16(v.w - __bfloat162float(hw)));
            const int off = row * ASTRIDE + c4 * 8;
            *(uint2*)(smem + SA_HI + off) = hp;
            *(uint2*)(smem + SA_LO + off) = lp;
        }
#pragma unroll
        for (int t = 0; t < 2; t++) {
            const int i = tid + t * 256, row = i >> 4, q = i & 15;
            const int off = row * BSTRIDE + q * 16;
            *(uint4*)(smem + SB_HI + off) = pbh[t];
            *(uint4*)(smem + SB_LO + off) = pbl[t];
        }
        __syncthreads();

        if (c + 1 < nc) { loadA((c + 1) << 5); loadB((c + 1) << 5); }

        // ---- MMA on current chunk (K=32 -> two k16 steps) ----
#pragma unroll
        for (int ks = 0; ks < 2; ks++) {
            uint32_t ah[4][4], al[4][4], bh[8], bl[8];
#pragma unroll
            for (int mi = 0; mi < 4; mi++) {
                const uint32_t ao = aAddr + (uint32_t)(mi * 16 * ASTRIDE + ks * 32);
                ldm_x4(ah[mi], ao + SA_HI);
                ldm_x4(al[mi], ao + SA_LO);
            }
#pragma unroll
            for (int j = 0; j < 2; j++) {   // j: n blocks of 16 within warp's 32
                const uint32_t bo = bAddr + (uint32_t)(ks * 16 * BSTRIDE + j * 32);
                ldm_x4t(bh + j * 4, bo);
                ldm_x4t(bl + j * 4, bo + (SB_LO - SB_HI));
            }
#pragma unroll
            for (int mi = 0; mi < 4; mi++)
#pragma unroll
                for (int nj = 0; nj < 4; nj++) {
                    mma16816(acc[mi][nj], ah[mi], bh + nj * 2);
                    mma16816(acc[mi][nj], ah[mi], bl + nj * 2);
                    mma16816(acc[mi][nj], al[mi], bh + nj * 2);
                }
        }
        __syncthreads();
    }

    // ---- epilogue ----
    const long gmBase = m0 + warpM + (lane >> 2);
    const int  gcBase = n0 + warpN + (lane & 3) * 2;
#pragma unroll
    for (int mi = 0; mi < 4; mi++) {
#pragma unroll
        for (int half = 0; half < 2; half++) {
            const long gr = gmBase + mi * 16 + half * 8;
            if (gr >= M) continue;
#pragma unroll
            for (int nj = 0; nj < 4; nj++) {
                const int gc = gcBase + nj * 8;
                if (gc >= realN) continue;
                float vx = acc[mi][nj][half * 2 + 0];
                float vy = acc[mi][nj][half * 2 + 1];
                if (bias) { vx += bias[gc]; vy += bias[gc + 1]; }
                if (Cin) {
                    const float2 cv = *(const float2*)(Cin + gr * (long)ldc + gc);
                    vx += cv.x; vy += cv.y;
                }
                if (doRelu) { vx = fmaxf(vx, 0.f); vy = fmaxf(vy, 0.f); }
                float2 o; o.x = vx; o.y = vy;
                *(float2*)(Out + gr * (long)ldc + gc) = o;
            }
        }
    }
}

// ---------------------------------------------------------------------------
// weight prep: W[K,N] fp32 -> bf16 hi/lo planes [Kp][Np] (same orientation)
// ---------------------------------------------------------------------------
__global__ __launch_bounds__(256)
void prep_weight(const float* __restrict__ W, __nv_bfloat16* __restrict__ hi,
                 __nv_bfloat16* __restrict__ lo, int K, int N, int Kpad, int Npad)
{
    const int i = blockIdx.x * blockDim.x + threadIdx.x;
    if (i >= Kpad * Npad) return;
    const int k = i / Npad, n = i % Npad;
    const float v = (k < K && n < N) ? W[(long)k * N + n] : 0.f;
    const __nv_bfloat16 h = __float2bfloat16(v);
    hi[i] = h;
    lo[i] = __float2bfloat16(v - __bfloat162float(h));
}

// ---------------------------------------------------------------------------
// h0[p,j] = relu(A[p/8,j] + sum_t rel[p,t]*W0c[t,j])
// ---------------------------------------------------------------------------
__global__ __launch_bounds__(256)
void point_layer0(const float* __restrict__ A, const float* __restrict__ rel,
                  const float* __restrict__ W0c, float* __restrict__ h0)
{
    const long idx = (long)blockIdx.x * blockDim.x + threadIdx.x;
    if (idx >= (long)M_PTS * 64) return;
    const long p = idx >> 6;
    const int j4 = (int)(idx & 63) << 2;
    const long node = p >> 3;

    const float r0 = rel[p * 3 + 0], r1 = rel[p * 3 + 1], r2 = rel[p * 3 + 2];
    const float4 a  = *(const float4*)(A + node * 256 + j4);
    const float4 w0 = *(const float4*)(W0c + 0   + j4);
    const float4 w1 = *(const float4*)(W0c + 256 + j4);
    const float4 w2 = *(const float4*)(W0c + 512 + j4);
    float4 o;
    o.x = fmaxf(a.x + r0 * w0.x + r1 * w1.x + r2 * w2.x, 0.f);
    o.y = fmaxf(a.y + r0 * w0.y + r1 * w1.y + r2 * w2.y, 0.f);
    o.z = fmaxf(a.z + r0 * w0.z + r1 * w1.z + r2 * w2.z, 0.f);
    o.w = fmaxf(a.w + r0 * w0.w + r1 * w1.w + r2 * w2.w, 0.f);
    *(float4*)(h0 + p * 256 + j4) = o;
}

__global__ __launch_bounds__(256)
void cluster_kernel(float* __restrict__ out)
{
    const int i = blockIdx.x * blockDim.x + threadIdx.x;
    if (i < M_PTS) out[i] = (float)(i >> 3);
}

// ---------------------------------------------------------------------------
// launch
// ---------------------------------------------------------------------------
extern "C" void kernel_launch(void* const* d_in, const int* in_sizes, int n_in,
                              void* d_out, int out_size)
{
    const float* X    = (const float*)d_in[0];
    const float* Wg0  = (const float*)d_in[1];
    const float* bg0  = (const float*)d_in[2];
    const float* Wg1  = (const float*)d_in[3];
    const float* bg1  = (const float*)d_in[4];
    const float* Wg2  = (const float*)d_in[5];
    const float* bg2  = (const float*)d_in[6];
    const float* Wdec = (const float*)d_in[7];
    const float* bdec = (const float*)d_in[8];
    const float* W0   = (const float*)d_in[9];
    const float* b0   = (const float*)d_in[10];
    const float* W1   = (const float*)d_in[11];
    const float* b1   = (const float*)d_in[12];
    const float* W2   = (const float*)d_in[13];
    const float* b2   = (const float*)d_in[14];

    float* out = (float*)d_out;
    float* out_rel     = out;
    float* out_decoded = out + 1200000;
    float* out_cluster = out + 1200000 + 102400000;

    float *h1, *h2, *feats, *T, *Abuf, *h0, *p1;
    __nv_bfloat16 *whi, *wlo;
    cudaGetSymbolAddress((void**)&h1,    g_h1);
    cudaGetSymbolAddress((void**)&h2,    g_h2);
    cudaGetSymbolAddress((void**)&feats, g_feats);
    cudaGetSymbolAddress((void**)&T,     g_T);
    cudaGetSymbolAddress((void**)&Abuf,  g_A);
    cudaGetSymbolAddress((void**)&h0,    g_h0);
    cudaGetSymbolAddress((void**)&p1,    g_p1);
    cudaGetSymbolAddress((void**)&whi,   g_whi);
    cudaGetSymbolAddress((void**)&wlo,   g_wlo);

    const float* W0a = W0;
    const float* W0b = W0 + 256 * 256;
    const float* W0c = W0 + 320 * 256;

    auto prep = [&](const float* W, int off, int K, int N, int Kp, int Np) {
        const int total = Kp * Np;
        prep_weight<<<(total + 255) / 256, 256>>>(W, whi + off, wlo + off, K, N, Kp, Np);
    };
    prep(Wg0,  OFF_WG0,  256, 256, 256, 256);
    prep(Wg1,  OFF_WG1,  256, 128, 256, 128);
    prep(Wg2,  OFF_WG2,  128,  64, 128, 128);
    prep(Wdec, OFF_WDEC,  64,  24,  64, 128);
    prep(W0a,  OFF_W0A,  256, 256, 256, 256);
    prep(W0b,  OFF_W0B,   64, 256,  64, 256);
    prep(W1,   OFF_W1,   256, 256, 256, 256);
    prep(W2,   OFF_W2,   256, 256, 256, 256);

    auto gemm = [&](const float* A, int off, const float* bias, const float* Cin,
                    float* Out, int M, int K, int Np, int realN, int ldc, int relu) {
        dim3 grid((realN + 127) / 128, (M + 127) / 128);
        gemm_mma<<<grid, 256>>>(A, whi + off, wlo + off, bias, Cin, Out,
                                M, K, Np, realN, ldc, relu);
    };

    // global MLP
    gemm(X,     OFF_WG0,  bg0,  nullptr, h1,    N_NODES, 256, 256, 256, 256, 1);
    gemm(h1,    OFF_WG1,  bg1,  nullptr, h2,    N_NODES, 256, 128, 128, 128, 1);
    gemm(h2,    OFF_WG2,  bg2,  nullptr, feats, N_NODES, 128, 128,  64,  64, 1);
    // decoder head -> relative_points
    gemm(feats, OFF_WDEC, bdec, nullptr, out_rel, N_NODES, 64, 128, 24, 24, 0);
    // node-level shared part of point-MLP layer 0
    gemm(X,     OFF_W0A,  b0,      nullptr, T,    N_NODES, 256, 256, 256, 256, 0);
    gemm(feats, OFF_W0B,  nullptr, T,       Abuf, N_NODES,  64, 256, 256, 256, 0);
    // per-point fold-in
    {
        const long total = (long)M_PTS * 64;
        point_layer0<<<(int)((total + 255) / 256), 256>>>(Abuf, out_rel, W0c, h0);
    }
    // point-MLP layers 1 & 2
    gemm(h0, OFF_W1, b1, nullptr, p1,          M_PTS, 256, 256, 256, 256, 1);
    gemm(p1, OFF_W2, b2, nullptr, out_decoded, M_PTS, 256, 256, 256, 256, 1);
    // cluster ids
    cluster_kernel<<<(M_PTS + 255) / 256, 256>>>(out_cluster);
}